// round 11
// baseline (speedup 1.0000x reference)
#include <cuda_runtime.h>
#include <cuda_fp16.h>
#include <math.h>
#include <stdint.h>

#define B_   64
#define L_   1024
#define ENC_ 2048
#define DEC_ 512
#define ATT_ 512
#define BL_  (B_ * L_)

// ---------------------------------------------------------------------------
// Device scratch
// ---------------------------------------------------------------------------
__device__ float g_H[B_ * ATT_];                          // proj_h + b2 + b1
// W1 fp16, layout [c=k/64][n 512][k 64]
__device__ __align__(128) __half g_B16[ENC_ * ATT_];
// F fp16 linear tiles [mb][c][row 128][k 64]  (context kernel)
__device__ __align__(128) __half g_F16[(size_t)BL_ * ENC_];
// F fp16 mma-fragment layout: unit = ((mb*32+c)*4+kk)*8+t, 512B per unit
// lane l holds {(r,k0),(r+8,k0),(r,k0+8),(r+8,k0+8)} half2s, r=t*16+(l>>2),
// k0 = kk*16 + (l&3)*2  (exactly the ldsm.x4 output of the R8 kernel)
__device__ __align__(128) __half g_Ffrag[(size_t)BL_ * ENC_];
__device__ float g_scorep[4 * BL_];                       // per-N-chunk score partials
__device__ float g_ctxp[8 * B_ * ENC_];                   // context partials

// ---------------------------------------------------------------------------
// Helpers
// ---------------------------------------------------------------------------
__device__ __forceinline__ uint32_t smem_u32(const void* p) {
    uint32_t a;
    asm("{ .reg .u64 t; cvta.to.shared.u64 t, %1; cvt.u32.u64 %0, t; }" : "=r"(a) : "l"(p));
    return a;
}
__device__ __forceinline__ void cp16(uint32_t dst, const void* src) {
    asm volatile("cp.async.cg.shared.global [%0], [%1], 16;" :: "r"(dst), "l"(src));
}
__device__ __forceinline__ void cp_commit() {
    asm volatile("cp.async.commit_group;" ::: "memory");
}
__device__ __forceinline__ void cp_wait1() {
    asm volatile("cp.async.wait_group 1;" ::: "memory");
}
__device__ __forceinline__ void ldsm_x4(uint32_t* r, uint32_t addr) {
    asm volatile("ldmatrix.sync.aligned.m8n8.x4.shared.b16 {%0,%1,%2,%3}, [%4];"
                 : "=r"(r[0]), "=r"(r[1]), "=r"(r[2]), "=r"(r[3]) : "r"(addr));
}
__device__ __forceinline__ void ldg128(uint32_t* r, const void* p) {
    asm volatile("ld.global.nc.v4.u32 {%0,%1,%2,%3}, [%4];"
                 : "=r"(r[0]), "=r"(r[1]), "=r"(r[2]), "=r"(r[3]) : "l"(p));
}
__device__ __forceinline__ void mma_f16(float* d, const uint32_t* a, const uint32_t* b) {
    asm volatile(
        "mma.sync.aligned.m16n8k16.row.col.f32.f16.f16.f32 "
        "{%0,%1,%2,%3}, {%4,%5,%6,%7}, {%8,%9}, {%0,%1,%2,%3};"
        : "+f"(d[0]), "+f"(d[1]), "+f"(d[2]), "+f"(d[3])
        : "r"(a[0]), "r"(a[1]), "r"(a[2]), "r"(a[3]), "r"(b[0]), "r"(b[1]));
}
__device__ __forceinline__ float fast_tanh(float x) {
    float e = __expf(2.f * x);
    return __fdividef(e - 1.f, e + 1.f);
}

// ---------------------------------------------------------------------------
// Kernel A: H = hidden @ W2 + b2 + b1
// ---------------------------------------------------------------------------
__global__ void proj_h_kernel(const float* __restrict__ hidden,
                              const float* __restrict__ W2,
                              const float* __restrict__ b2,
                              const float* __restrict__ b1) {
    __shared__ float hs[DEC_];
    int b = blockIdx.x, a = threadIdx.x;
    hs[a] = hidden[b * DEC_ + a];
    __syncthreads();
    float acc = 0.f;
#pragma unroll 8
    for (int d = 0; d < DEC_; ++d) acc += hs[d] * W2[d * ATT_ + a];
    g_H[b * ATT_ + a] = acc + b2[a] + b1[a];
}

// ---------------------------------------------------------------------------
// Kernel B1: W1 [ENC, ATT] fp32 -> fp16, layout [c][n][k64]
// ---------------------------------------------------------------------------
__global__ void prep_B_kernel(const float* __restrict__ W1) {
    int idx = blockIdx.x * 256 + threadIdx.x;   // idx = k*512 + n
    if (idx >= ENC_ * ATT_) return;
    int k = idx >> 9, n = idx & 511;
    int c = k >> 6, kk = k & 63;
    g_B16[((size_t)(c * 512 + n) << 6) + kk] = __float2half_rn(W1[idx]);
}

// ---------------------------------------------------------------------------
// Kernel B2: F -> fp16 in BOTH linear tiles and mma-fragment layout.
// One block per (c, mb): stages a 128x64 chunk through smem.
// ---------------------------------------------------------------------------
__global__ __launch_bounds__(256) void prep_F_kernel(const float* __restrict__ F) {
    __shared__ __half sF[128 * 72];    // pitch 72 halves = 144B
    const int c  = blockIdx.x;         // 0..31
    const int mb = blockIdx.y;         // 0..511
    const int tid = threadIdx.x;
    const int lane = tid & 31, wid = tid >> 5;
    const int m0 = mb * 128;

    // load 128 rows x 64 k fp32, convert, write linear copy
#pragma unroll
    for (int e = 0; e < 8; ++e) {
        int j = tid + e * 256, row = j >> 4, q = j & 15;   // q = float4 within row
        float4 f = *(const float4*)(F + (size_t)(m0 + row) * ENC_ + c * 64 + q * 4);
        __half2 h01 = __floats2half2_rn(f.x, f.y);
        __half2 h23 = __floats2half2_rn(f.z, f.w);
        uint2 v = make_uint2(*(uint32_t*)&h01, *(uint32_t*)&h23);
        *(uint2*)(&sF[row * 72 + q * 4]) = v;
        *(uint2*)(g_F16 + (((size_t)(mb * 32 + c) * 128 + row) << 6) + q * 4) = v;
    }
    __syncthreads();

    // write fragment layout: 32 units (4 kk x 8 t), 4 per warp
#pragma unroll
    for (int u = 0; u < 4; ++u) {
        int unit = wid * 4 + u;
        int kk = unit >> 3, t = unit & 7;
        int r  = t * 16 + (lane >> 2);
        int k0 = kk * 16 + (lane & 3) * 2;
        uint32_t v0 = *(const uint32_t*)(&sF[r * 72 + k0]);
        uint32_t v1 = *(const uint32_t*)(&sF[(r + 8) * 72 + k0]);
        uint32_t v2 = *(const uint32_t*)(&sF[r * 72 + k0 + 8]);
        uint32_t v3 = *(const uint32_t*)(&sF[(r + 8) * 72 + k0 + 8]);
        size_t off = ((((size_t)(mb * 32 + c) * 4 + kk) * 8 + t) << 8) + lane * 8;  // halves
        *(uint4*)(g_Ffrag + off) = make_uint4(v0, v1, v2, v3);
    }
}

// ---------------------------------------------------------------------------
// Kernel C: fused fp16 mma.sync GEMM + tanh + V-reduction -> score partials
// Grid: (4 nc, 512 m) nc-major. CTA: 128x128, 256 thr, KC=64.
// A: gmem fragment layout, LDG.128 software-pipelined 2 slabs ahead (no smem).
// B: 3-stage cp.async smem + ldsm. 2 CTAs/SM.
// ---------------------------------------------------------------------------
static constexpr int PITCH  = 144;            // 128B data + 16B pad
static constexpr int TILE   = 128 * PITCH;    // 18432 (B tile only)
static constexpr int NSTG   = 3;
static constexpr int OFF_PART = NSTG * TILE;          // 55296
static constexpr int OFF_H    = OFF_PART + 1024;
static constexpr int OFF_V    = OFF_H + 512;
static constexpr int SMEM_TOTAL = OFF_V + 512;        // 57344
static constexpr int NCHUNK = ENC_ / 64;              // 32
static constexpr int B_STRIDE = 512 * 64;             // halves per chunk

__global__ __launch_bounds__(256, 2) void score_mma_kernel(const float* __restrict__ V)
{
    extern __shared__ char smem[];
    const uint32_t sb = smem_u32(smem);
    const int tid  = threadIdx.x;
    const int lane = tid & 31;
    const int wid  = tid >> 5;
    const int wm   = wid & 3;        // warp m: 4 x 32 rows
    const int wn   = wid >> 2;       // warp n: 2 x 64 cols
    const int nc   = blockIdx.x;     // n chunk (128 cols)
    const int mb   = blockIdx.y;
    const int m0   = mb * 128;
    const int b    = mb >> 3;

    float* partS = (float*)(smem + OFF_PART);
    float* Hs    = (float*)(smem + OFF_H);
    float* Vs    = (float*)(smem + OFF_V);
    if (tid < 128) {
        Hs[tid] = g_H[b * ATT_ + nc * 128 + tid];
        Vs[tid] = V[nc * 128 + tid];
    }

    float d[2][8][4];
#pragma unroll
    for (int mt = 0; mt < 2; ++mt)
#pragma unroll
        for (int nt = 0; nt < 8; ++nt)
#pragma unroll
            for (int e = 0; e < 4; ++e) d[mt][nt][e] = 0.f;

    // B cp.async state: 4 x 16B per thread per chunk
    uint32_t dsto[4];
    const __half* pB[4];
#pragma unroll
    for (int e = 0; e < 4; ++e) {
        int j = tid + e * 256, row = j >> 3, q = j & 7;
        dsto[e] = (uint32_t)(row * PITCH + q * 16);
        pB[e] = g_B16 + (((size_t)(nc * 128 + row)) << 6) + q * 8;
    }

    // A fragment pointers: per mt, per slab stride 4096B
    const char* pAf0 = (const char*)g_Ffrag +
        (((size_t)mb * 128 * 8 + wm * 2 + 0) << 9) + lane * 16;
    const char* pAf1 = pAf0 + 512;     // mt=1 unit

    // ---- prologue: B chunks 0,1 -> stages 0,1; A slabs 0,1 -> regs ----
#pragma unroll
    for (int cch = 0; cch < 2; ++cch) {
        const uint32_t stg = sb + cch * TILE;
#pragma unroll
        for (int e = 0; e < 4; ++e) { cp16(stg + dsto[e], pB[e]); pB[e] += B_STRIDE; }
        cp_commit();
    }
    uint32_t af[2][2][4];
    ldg128(af[0][0], pAf0);            ldg128(af[0][1], pAf1);
    ldg128(af[1][0], pAf0 + 4096);     ldg128(af[1][1], pAf1 + 4096);
    pAf0 += 8192;  pAf1 += 8192;       // next load = slab 2

    // hoisted B ldsm offsets (stage-relative)
    uint32_t boff[4];
#pragma unroll
    for (int p = 0; p < 4; ++p)
        boff[p] = (uint32_t)(wn * 64 + p * 16 + (lane & 15)) * PITCH +
                  (uint32_t)(((lane >> 4) & 1) * 16);

    int cs = 0, ps = 2;   // compute stage, prefetch stage
#pragma unroll 1
    for (int i = 0; i < NCHUNK; ++i) {
        const uint32_t stg = sb + cs * TILE;
        if (++cs == NSTG) cs = 0;

        cp_wait1();
        __syncthreads();

        if (i + 2 < NCHUNK) {
            const uint32_t nstg = sb + ps * TILE;
            if (++ps == NSTG) ps = 0;
#pragma unroll
            for (int e = 0; e < 4; ++e) { cp16(nstg + dsto[e], pB[e]); pB[e] += B_STRIDE; }
            cp_commit();
        }

        // ---- compute chunk i: 4 k16 slabs ----
#pragma unroll
        for (int kk = 0; kk < 4; ++kk) {
            const uint32_t ko = (uint32_t)(kk * 32);
            const int buf = kk & 1;
            uint32_t bb[8][2];
#pragma unroll
            for (int p = 0; p < 4; ++p) {       // paired ldsm: 2 n-tiles per x4
                uint32_t r[4];
                ldsm_x4(r, stg + boff[p] + ko);
                bb[2 * p][0]     = r[0];
                bb[2 * p + 1][0] = r[1];
                bb[2 * p][1]     = r[2];
                bb[2 * p + 1][1] = r[3];
            }
#pragma unroll
            for (int nt = 0; nt < 8; ++nt) {
                mma_f16(d[0][nt], af[buf][0], bb[nt]);
                mma_f16(d[1][nt], af[buf][1], bb[nt]);
            }
            if (i < NCHUNK - 1 || kk < 2) {     // load slab i*4+kk+2
                ldg128(af[buf][0], pAf0);  pAf0 += 4096;
                ldg128(af[buf][1], pAf1);  pAf1 += 4096;
            }
        }
    }

    // ---- epilogue: tanh + V-weighted row reduction over this 128-col chunk ----
#pragma unroll
    for (int mt = 0; mt < 2; ++mt) {
        float s0 = 0.f, s1 = 0.f;
#pragma unroll
        for (int nt = 0; nt < 8; ++nt) {
            int c0 = wn * 64 + nt * 8 + (lane & 3) * 2;
            float h0 = Hs[c0], v0 = Vs[c0];
            float h1 = Hs[c0 + 1], v1 = Vs[c0 + 1];
            s0 += fast_tanh(d[mt][nt][0] + h0) * v0 + fast_tanh(d[mt][nt][1] + h1) * v1;
            s1 += fast_tanh(d[mt][nt][2] + h0) * v0 + fast_tanh(d[mt][nt][3] + h1) * v1;
        }
#pragma unroll
        for (int o = 1; o <= 2; o <<= 1) {
            s0 += __shfl_xor_sync(~0u, s0, o);
            s1 += __shfl_xor_sync(~0u, s1, o);
        }
        if ((lane & 3) == 0) {
            int r = wm * 32 + mt * 16 + (lane >> 2);
            partS[wn * 128 + r]     = s0;
            partS[wn * 128 + r + 8] = s1;
        }
    }
    __syncthreads();
    if (tid < 128)
        g_scorep[nc * BL_ + m0 + tid] = partS[tid] + partS[128 + tid];
}

// ---------------------------------------------------------------------------
// Kernel D: combine partials + softmax over L per batch
// ---------------------------------------------------------------------------
__global__ void softmax_kernel(const float* __restrict__ bv, float* __restrict__ w) {
    __shared__ float redm[32];
    __shared__ float reds[32];
    const int b = blockIdx.x, t = threadIdx.x;
    const int idx = b * L_ + t;
    float s = g_scorep[idx] + g_scorep[BL_ + idx] + g_scorep[2 * BL_ + idx] +
              g_scorep[3 * BL_ + idx] + bv[0];
    float m = s;
#pragma unroll
    for (int o = 16; o > 0; o >>= 1) m = fmaxf(m, __shfl_xor_sync(~0u, m, o));
    if ((t & 31) == 0) redm[t >> 5] = m;
    __syncthreads();
    if (t < 32) {
        float v = redm[t];
#pragma unroll
        for (int o = 16; o > 0; o >>= 1) v = fmaxf(v, __shfl_xor_sync(~0u, v, o));
        redm[t] = v;
    }
    __syncthreads();
    m = redm[0];
    const float e = expf(s - m);
    float sum = e;
#pragma unroll
    for (int o = 16; o > 0; o >>= 1) sum += __shfl_xor_sync(~0u, sum, o);
    if ((t & 31) == 0) reds[t >> 5] = sum;
    __syncthreads();
    if (t < 32) {
        float v = reds[t];
#pragma unroll
        for (int o = 16; o > 0; o >>= 1) v += __shfl_xor_sync(~0u, v, o);
        reds[t] = v;
    }
    __syncthreads();
    w[idx] = e / reds[0];
}

// ---------------------------------------------------------------------------
// Kernel E/F: context = sum_l w*F  (fp16 linear tiles; 8 L-partials + reduce)
// ---------------------------------------------------------------------------
__global__ void context_part_kernel(const float* __restrict__ w) {
    __shared__ float ws[128];
    const int b = blockIdx.y, z = blockIdx.z, t = threadIdx.x;
    ws[t] = w[b * L_ + z * 128 + t];
    __syncthreads();
    const int e0 = blockIdx.x * 512 + t * 4;
    const int mb = b * 8 + z;
    const int c  = e0 >> 6, kk = e0 & 63;
    const __half* base = g_F16 + (((size_t)(mb * 32 + c) * 128) << 6) + kk;
    float4 acc = make_float4(0.f, 0.f, 0.f, 0.f);
#pragma unroll 4
    for (int l = 0; l < 128; ++l) {
        uint2 v = *(const uint2*)(base + ((size_t)l << 6));
        float2 f01 = __half22float2(*(const __half2*)&v.x);
        float2 f23 = __half22float2(*(const __half2*)&v.y);
        const float wl = ws[l];
        acc.x += wl * f01.x; acc.y += wl * f01.y;
        acc.z += wl * f23.x; acc.w += wl * f23.y;
    }
    *(float4*)&g_ctxp[(size_t)(z * B_ + b) * ENC_ + e0] = acc;
}

__global__ void context_reduce_kernel(float* __restrict__ ctx) {
    const int i = (blockIdx.x * 256 + threadIdx.x) * 4;
    float4 acc = make_float4(0.f, 0.f, 0.f, 0.f);
#pragma unroll
    for (int p = 0; p < 8; ++p) {
        float4 a = *(const float4*)&g_ctxp[(size_t)p * B_ * ENC_ + i];
        acc.x += a.x; acc.y += a.y; acc.z += a.z; acc.w += a.w;
    }
    *(float4*)&ctx[i] = acc;
}

// ---------------------------------------------------------------------------
// Launch
// ---------------------------------------------------------------------------
extern "C" void kernel_launch(void* const* d_in, const int* in_sizes, int n_in,
                              void* d_out, int out_size) {
    const float* F   = (const float*)d_in[0];
    const float* hid = (const float*)d_in[1];
    const float* W1  = (const float*)d_in[2];
    const float* b1  = (const float*)d_in[3];
    const float* W2  = (const float*)d_in[4];
    const float* b2  = (const float*)d_in[5];
    const float* V   = (const float*)d_in[6];
    const float* bv  = (const float*)d_in[7];

    float* out = (float*)d_out;
    float* ctx = out;
    float* wts = out + B_ * ENC_;

    cudaFuncSetAttribute(score_mma_kernel,
                         cudaFuncAttributeMaxDynamicSharedMemorySize, SMEM_TOTAL);

    proj_h_kernel<<<B_, ATT_>>>(hid, W2, b2, b1);
    prep_B_kernel<<<(ENC_ * ATT_) / 256, 256>>>(W1);
    prep_F_kernel<<<dim3(32, 512), 256>>>(F);
    score_mma_kernel<<<dim3(4, BL_ / 128), 256, SMEM_TOTAL>>>(V);
    softmax_kernel<<<B_, L_>>>(bv, wts);
    context_part_kernel<<<dim3(ENC_ / 512, B_, 8), 128>>>(wts);
    context_reduce_kernel<<<(B_ * ENC_) / 1024, 256>>>(ctx);
}

// round 12
// speedup vs baseline: 1.0359x; 1.0359x over previous
#include <cuda_runtime.h>
#include <cuda_fp16.h>
#include <math.h>
#include <stdint.h>

#define B_   64
#define L_   1024
#define ENC_ 2048
#define DEC_ 512
#define ATT_ 512
#define BL_  (B_ * L_)

// ---------------------------------------------------------------------------
// Device scratch
// ---------------------------------------------------------------------------
__device__ float g_H[B_ * ATT_];                          // proj_h + b2 + b1
// W1 fp16, layout [c=k/32][n 512][k 32]
__device__ __align__(128) __half g_B16[ENC_ * ATT_];
__device__ float g_scorep[4 * BL_];                       // per-N-chunk score partials
__device__ float g_ctxp[8 * B_ * ENC_];                   // context partials

// ---------------------------------------------------------------------------
// Helpers
// ---------------------------------------------------------------------------
__device__ __forceinline__ uint32_t smem_u32(const void* p) {
    uint32_t a;
    asm("{ .reg .u64 t; cvta.to.shared.u64 t, %1; cvt.u32.u64 %0, t; }" : "=r"(a) : "l"(p));
    return a;
}
__device__ __forceinline__ void cp16(uint32_t dst, const void* src) {
    asm volatile("cp.async.cg.shared.global [%0], [%1], 16;" :: "r"(dst), "l"(src));
}
__device__ __forceinline__ void cp_commit() {
    asm volatile("cp.async.commit_group;" ::: "memory");
}
__device__ __forceinline__ void cp_wait1() {
    asm volatile("cp.async.wait_group 1;" ::: "memory");
}
__device__ __forceinline__ void ldsm_x4(uint32_t* r, uint32_t addr) {
    asm volatile("ldmatrix.sync.aligned.m8n8.x4.shared.b16 {%0,%1,%2,%3}, [%4];"
                 : "=r"(r[0]), "=r"(r[1]), "=r"(r[2]), "=r"(r[3]) : "r"(addr));
}
__device__ __forceinline__ uint32_t lds_cvt(uint32_t addr) {
    float x, y;
    asm volatile("ld.shared.v2.f32 {%0,%1}, [%2];" : "=f"(x), "=f"(y) : "r"(addr));
    __half2 h = __floats2half2_rn(x, y);
    return *(uint32_t*)&h;
}
__device__ __forceinline__ void mma_f16(float* d, const uint32_t* a, const uint32_t* b) {
    asm volatile(
        "mma.sync.aligned.m16n8k16.row.col.f32.f16.f16.f32 "
        "{%0,%1,%2,%3}, {%4,%5,%6,%7}, {%8,%9}, {%0,%1,%2,%3};"
        : "+f"(d[0]), "+f"(d[1]), "+f"(d[2]), "+f"(d[3])
        : "r"(a[0]), "r"(a[1]), "r"(a[2]), "r"(a[3]), "r"(b[0]), "r"(b[1]));
}
__device__ __forceinline__ float fast_tanh(float x) {
    float e = __expf(2.f * x);
    return __fdividef(e - 1.f, e + 1.f);
}

// ---------------------------------------------------------------------------
// Kernel A: H = hidden @ W2 + b2 + b1
// ---------------------------------------------------------------------------
__global__ void proj_h_kernel(const float* __restrict__ hidden,
                              const float* __restrict__ W2,
                              const float* __restrict__ b2,
                              const float* __restrict__ b1) {
    __shared__ float hs[DEC_];
    int b = blockIdx.x, a = threadIdx.x;
    hs[a] = hidden[b * DEC_ + a];
    __syncthreads();
    float acc = 0.f;
#pragma unroll 8
    for (int d = 0; d < DEC_; ++d) acc += hs[d] * W2[d * ATT_ + a];
    g_H[b * ATT_ + a] = acc + b2[a] + b1[a];
}

// ---------------------------------------------------------------------------
// Kernel B: W1 [ENC, ATT] fp32 -> fp16, layout [c=k/32][n][k32]
// ---------------------------------------------------------------------------
__global__ void prep_B_kernel(const float* __restrict__ W1) {
    int idx = blockIdx.x * 256 + threadIdx.x;   // idx = k*512 + n
    if (idx >= ENC_ * ATT_) return;
    int k = idx >> 9, n = idx & 511;
    int c = k >> 5, kk = k & 31;
    g_B16[((size_t)(c * 512 + n) << 5) + kk] = __float2half_rn(W1[idx]);
}

// ---------------------------------------------------------------------------
// Kernel C: fused fp16 mma.sync GEMM + tanh + V-reduction -> score partials
// Grid: (4 nc, 512 m) nc-major. CTA: 128x128, 256 thr, KC=32, 3 stages.
// A: fp32 staged via cp.async; fragments built with LDS.64 + cvt (no prep_F!).
// B: fp16 cp.async + ldsm. 2 CTAs/SM.
// ---------------------------------------------------------------------------
static constexpr int A_PITCH = 160;             // 128B fp32 data + 32B pad
static constexpr int B_PITCH = 80;              // 64B fp16 data + 16B pad
static constexpr int A_TILE  = 128 * A_PITCH;   // 20480
static constexpr int B_TILE  = 128 * B_PITCH;   // 10240
static constexpr int STAGE   = A_TILE + B_TILE; // 30720
static constexpr int NSTG    = 3;
static constexpr int OFF_A   = 0;
static constexpr int OFF_B   = A_TILE;
static constexpr int OFF_PART = NSTG * STAGE;          // 92160
static constexpr int OFF_H    = OFF_PART + 1024;
static constexpr int OFF_V    = OFF_H + 512;
static constexpr int SMEM_TOTAL = OFF_V + 512;         // 94208
static constexpr int NCHUNK  = ENC_ / 32;              // 64

__global__ __launch_bounds__(256, 2) void score_mma_kernel(
    const float* __restrict__ F, const float* __restrict__ V)
{
    extern __shared__ char smem[];
    const uint32_t sb = smem_u32(smem);
    const int tid  = threadIdx.x;
    const int lane = tid & 31;
    const int wid  = tid >> 5;
    const int wm   = wid & 3;        // warp m: 4 x 32 rows
    const int wn   = wid >> 2;       // warp n: 2 x 64 cols
    const int nc   = blockIdx.x;     // n chunk (128 cols)
    const int mb   = blockIdx.y;
    const int m0   = mb * 128;
    const int b    = mb >> 3;

    float* partS = (float*)(smem + OFF_PART);
    float* Hs    = (float*)(smem + OFF_H);
    float* Vs    = (float*)(smem + OFF_V);
    if (tid < 128) {
        Hs[tid] = g_H[b * ATT_ + nc * 128 + tid];
        Vs[tid] = V[nc * 128 + tid];
    }

    float d[2][8][4];
#pragma unroll
    for (int mt = 0; mt < 2; ++mt)
#pragma unroll
        for (int nt = 0; nt < 8; ++nt)
#pragma unroll
            for (int e = 0; e < 4; ++e) d[mt][nt][e] = 0.f;

    // cp.async assignments (base + 32-bit offsets to save regs)
    // A: 1024 x 16B units: j = tid + e*256 (e<4), row=j>>3, q=j&7
    // B: 512 x 16B units : j = tid + e*256 (e<2), row=j>>2, q=j&3
    const char* Abase = (const char*)(F + (size_t)m0 * ENC_);     // +128B/chunk
    const char* Bbase = (const char*)(g_B16 + ((size_t)(nc * 128) << 5)); // +32KB/chunk
    uint32_t aSrc[4], aDst[4], bSrc[2], bDst[2];
#pragma unroll
    for (int e = 0; e < 4; ++e) {
        int j = tid + e * 256, row = j >> 3, q = j & 7;
        aSrc[e] = (uint32_t)(row * (ENC_ * 4) + q * 16);
        aDst[e] = (uint32_t)(OFF_A + row * A_PITCH + q * 16);
    }
#pragma unroll
    for (int e = 0; e < 2; ++e) {
        int j = tid + e * 256, row = j >> 2, q = j & 3;
        bSrc[e] = (uint32_t)(row * 64 + q * 16);
        bDst[e] = (uint32_t)(OFF_B + row * B_PITCH + q * 16);
    }

    // ---- prologue: chunks 0,1 -> stages 0,1 ----
#pragma unroll
    for (int c = 0; c < 2; ++c) {
        const uint32_t stg = sb + c * STAGE;
#pragma unroll
        for (int e = 0; e < 4; ++e) cp16(stg + aDst[e], Abase + aSrc[e]);
#pragma unroll
        for (int e = 0; e < 2; ++e) cp16(stg + bDst[e], Bbase + bSrc[e]);
        cp_commit();
        Abase += 128;          // next 32 fp32 k
        Bbase += 32768;        // next chunk of B (512*32 halves)
    }

    // A fragment LDS bases (stage-relative): row = wm*32 + mt*16 + (lane>>2)
    const uint32_t aL0 = OFF_A + (uint32_t)(wm * 32 + (lane >> 2)) * A_PITCH +
                         (uint32_t)((lane & 3) * 8);
    const uint32_t aL1 = aL0 + 16 * A_PITCH;   // mt = 1
    // B ldsm bases
    uint32_t boff[4];
#pragma unroll
    for (int p = 0; p < 4; ++p)
        boff[p] = OFF_B + (uint32_t)(wn * 64 + p * 16 + (lane & 15)) * B_PITCH +
                  (uint32_t)(((lane >> 4) & 1) * 16);

    int cs = 0, ps = 2;
#pragma unroll 1
    for (int i = 0; i < NCHUNK; ++i) {
        const uint32_t stg = sb + cs * STAGE;
        if (++cs == NSTG) cs = 0;

        cp_wait1();
        __syncthreads();

        if (i + 2 < NCHUNK) {
            const uint32_t nstg = sb + ps * STAGE;
            if (++ps == NSTG) ps = 0;
#pragma unroll
            for (int e = 0; e < 4; ++e) cp16(nstg + aDst[e], Abase + aSrc[e]);
#pragma unroll
            for (int e = 0; e < 2; ++e) cp16(nstg + bDst[e], Bbase + bSrc[e]);
            cp_commit();
            Abase += 128;
            Bbase += 32768;
        }

        // ---- compute chunk i: 2 k16 slabs ----
#pragma unroll
        for (int kk = 0; kk < 2; ++kk) {
            const uint32_t akk = (uint32_t)(kk * 64);   // 16 fp32 = 64B
            const uint32_t bkk = (uint32_t)(kk * 32);   // 16 fp16 = 32B
            // A fragments via LDS.64 + cvt  (identical values to ldsm-on-fp16)
            uint32_t a0[4], a1[4];
            {
                uint32_t base0 = stg + aL0 + akk;
                a0[0] = lds_cvt(base0);
                a0[1] = lds_cvt(base0 + 8 * A_PITCH);
                a0[2] = lds_cvt(base0 + 32);
                a0[3] = lds_cvt(base0 + 8 * A_PITCH + 32);
                uint32_t base1 = stg + aL1 + akk;
                a1[0] = lds_cvt(base1);
                a1[1] = lds_cvt(base1 + 8 * A_PITCH);
                a1[2] = lds_cvt(base1 + 32);
                a1[3] = lds_cvt(base1 + 8 * A_PITCH + 32);
            }
            uint32_t bb[8][2];
#pragma unroll
            for (int p = 0; p < 4; ++p) {
                uint32_t r[4];
                ldsm_x4(r, stg + boff[p] + bkk);
                bb[2 * p][0]     = r[0];
                bb[2 * p + 1][0] = r[1];
                bb[2 * p][1]     = r[2];
                bb[2 * p + 1][1] = r[3];
            }
#pragma unroll
            for (int nt = 0; nt < 8; ++nt) {
                mma_f16(d[0][nt], a0, bb[nt]);
                mma_f16(d[1][nt], a1, bb[nt]);
            }
        }
    }

    // ---- epilogue: tanh + V-weighted row reduction over this 128-col chunk ----
#pragma unroll
    for (int mt = 0; mt < 2; ++mt) {
        float s0 = 0.f, s1 = 0.f;
#pragma unroll
        for (int nt = 0; nt < 8; ++nt) {
            int c0 = wn * 64 + nt * 8 + (lane & 3) * 2;
            float h0 = Hs[c0], v0 = Vs[c0];
            float h1 = Hs[c0 + 1], v1 = Vs[c0 + 1];
            s0 += fast_tanh(d[mt][nt][0] + h0) * v0 + fast_tanh(d[mt][nt][1] + h1) * v1;
            s1 += fast_tanh(d[mt][nt][2] + h0) * v0 + fast_tanh(d[mt][nt][3] + h1) * v1;
        }
#pragma unroll
        for (int o = 1; o <= 2; o <<= 1) {
            s0 += __shfl_xor_sync(~0u, s0, o);
            s1 += __shfl_xor_sync(~0u, s1, o);
        }
        if ((lane & 3) == 0) {
            int r = wm * 32 + mt * 16 + (lane >> 2);
            partS[wn * 128 + r]     = s0;
            partS[wn * 128 + r + 8] = s1;
        }
    }
    __syncthreads();
    if (tid < 128)
        g_scorep[nc * BL_ + m0 + tid] = partS[tid] + partS[128 + tid];
}

// ---------------------------------------------------------------------------
// Kernel D: combine partials + softmax over L per batch
// ---------------------------------------------------------------------------
__global__ void softmax_kernel(const float* __restrict__ bv, float* __restrict__ w) {
    __shared__ float redm[32];
    __shared__ float reds[32];
    const int b = blockIdx.x, t = threadIdx.x;
    const int idx = b * L_ + t;
    float s = g_scorep[idx] + g_scorep[BL_ + idx] + g_scorep[2 * BL_ + idx] +
              g_scorep[3 * BL_ + idx] + bv[0];
    float m = s;
#pragma unroll
    for (int o = 16; o > 0; o >>= 1) m = fmaxf(m, __shfl_xor_sync(~0u, m, o));
    if ((t & 31) == 0) redm[t >> 5] = m;
    __syncthreads();
    if (t < 32) {
        float v = redm[t];
#pragma unroll
        for (int o = 16; o > 0; o >>= 1) v = fmaxf(v, __shfl_xor_sync(~0u, v, o));
        redm[t] = v;
    }
    __syncthreads();
    m = redm[0];
    const float e = expf(s - m);
    float sum = e;
#pragma unroll
    for (int o = 16; o > 0; o >>= 1) sum += __shfl_xor_sync(~0u, sum, o);
    if ((t & 31) == 0) reds[t >> 5] = sum;
    __syncthreads();
    if (t < 32) {
        float v = reds[t];
#pragma unroll
        for (int o = 16; o > 0; o >>= 1) v += __shfl_xor_sync(~0u, v, o);
        reds[t] = v;
    }
    __syncthreads();
    w[idx] = e / reds[0];
}

// ---------------------------------------------------------------------------
// Kernel E/F: context = sum_l w*F  (fp32 F; 8 L-partials, then reduced)
// ---------------------------------------------------------------------------
__global__ void context_part_kernel(const float* __restrict__ F,
                                    const float* __restrict__ w) {
    __shared__ float ws[128];
    const int b = blockIdx.y, z = blockIdx.z, t = threadIdx.x;
    const int l0 = z * 128;
    ws[t] = w[b * L_ + l0 + t];
    __syncthreads();
    const int e0 = blockIdx.x * 512 + t * 4;
    const float* fb = F + (size_t)b * L_ * ENC_ + (size_t)l0 * ENC_ + e0;
    float4 acc = make_float4(0.f, 0.f, 0.f, 0.f);
#pragma unroll 4
    for (int l = 0; l < 128; ++l) {
        float4 f = *(const float4*)(fb + (size_t)l * ENC_);
        const float wl = ws[l];
        acc.x += wl * f.x; acc.y += wl * f.y; acc.z += wl * f.z; acc.w += wl * f.w;
    }
    *(float4*)&g_ctxp[(size_t)(z * B_ + b) * ENC_ + e0] = acc;
}

__global__ void context_reduce_kernel(float* __restrict__ ctx) {
    const int i = (blockIdx.x * 256 + threadIdx.x) * 4;
    float4 acc = make_float4(0.f, 0.f, 0.f, 0.f);
#pragma unroll
    for (int p = 0; p < 8; ++p) {
        float4 a = *(const float4*)&g_ctxp[(size_t)p * B_ * ENC_ + i];
        acc.x += a.x; acc.y += a.y; acc.z += a.z; acc.w += a.w;
    }
    *(float4*)&ctx[i] = acc;
}

// ---------------------------------------------------------------------------
// Launch
// ---------------------------------------------------------------------------
extern "C" void kernel_launch(void* const* d_in, const int* in_sizes, int n_in,
                              void* d_out, int out_size) {
    const float* F   = (const float*)d_in[0];
    const float* hid = (const float*)d_in[1];
    const float* W1  = (const float*)d_in[2];
    const float* b1  = (const float*)d_in[3];
    const float* W2  = (const float*)d_in[4];
    const float* b2  = (const float*)d_in[5];
    const float* V   = (const float*)d_in[6];
    const float* bv  = (const float*)d_in[7];

    float* out = (float*)d_out;
    float* ctx = out;
    float* wts = out + B_ * ENC_;

    cudaFuncSetAttribute(score_mma_kernel,
                         cudaFuncAttributeMaxDynamicSharedMemorySize, SMEM_TOTAL);

    proj_h_kernel<<<B_, ATT_>>>(hid, W2, b2, b1);
    prep_B_kernel<<<(ENC_ * ATT_) / 256, 256>>>(W1);
    score_mma_kernel<<<dim3(4, BL_ / 128), 256, SMEM_TOTAL>>>(F, V);
    softmax_kernel<<<B_, L_>>>(bv, wts);
    context_part_kernel<<<dim3(ENC_ / 512, B_, 8), 128>>>(F, wts);
    context_reduce_kernel<<<(B_ * ENC_) / 1024, 256>>>(ctx);
}